// round 16
// baseline (speedup 1.0000x reference)
#include <cuda_runtime.h>
#include <cstdint>

// RGCNHighMem: out[dst] += feat[src] @ W[etype]
// v16: v14 split-bf16 mma.sync main (EPB 256, rolling prefetch) with:
//  - occ 5 (all B fragments ldsm'd per tile; regs under the occ-5 cap)
//  - g_cnt self-zeroing at end of k_main (g_done counter) -> no memset launch

#define RELS   64
#define EPB    256
#define SCHUNK 256
#define CAP    8192
#define MAXK   (CAP / EPB)  // 32
#define NBLK   (RELS * MAXK)

__device__ int g_cnt[RELS];        // zero-init; restored to zero each call
__device__ int g_done;             // zero-init; restored to zero each call
__device__ unsigned long long g_edges[RELS * CAP];  // packed (src | dst<<32)

__device__ __forceinline__ uint32_t smem_u32(const void* p) {
    uint32_t a;
    asm("{ .reg .u64 t; cvta.to.shared.u64 t, %1; cvt.u32.u64 %0, t; }"
        : "=r"(a) : "l"(p));
    return a;
}
__device__ __forceinline__ uint32_t pack_bf16x2(float lo, float hi) {
    uint32_t r;
    asm("cvt.rn.bf16x2.f32 %0, %1, %2;" : "=r"(r) : "f"(hi), "f"(lo));
    return r;
}
__device__ __forceinline__ void ldsm4(uint32_t a, uint32_t* f) {
    asm volatile("ldmatrix.sync.aligned.m8n8.x4.shared.b16 {%0,%1,%2,%3}, [%4];"
                 : "=r"(f[0]), "=r"(f[1]), "=r"(f[2]), "=r"(f[3]) : "r"(a));
}
__device__ __forceinline__ void mma16816(float* d, const uint32_t* a,
                                         const uint32_t* b) {
    asm volatile(
        "mma.sync.aligned.m16n8k16.row.col.f32.bf16.bf16.f32 "
        "{%0,%1,%2,%3}, {%4,%5,%6,%7}, {%8,%9}, {%0,%1,%2,%3};"
        : "+f"(d[0]), "+f"(d[1]), "+f"(d[2]), "+f"(d[3])
        : "r"(a[0]), "r"(a[1]), "r"(a[2]), "r"(a[3]), "r"(b[0]), "r"(b[1]));
}

// Single-pass scatter + d_out zeroing; 1 edge/thread.
__global__ __launch_bounds__(256)
void k_scatter(const int* __restrict__ src, const int* __restrict__ dst,
               const int* __restrict__ et, int E,
               float4* __restrict__ out4, int nout4) {
    __shared__ int cnt[RELS], base[RELS];
    int tid = threadIdx.x;

    for (int i = blockIdx.x * 256 + tid; i < nout4; i += gridDim.x * 256)
        out4[i] = make_float4(0.f, 0.f, 0.f, 0.f);

    int e = blockIdx.x * SCHUNK + tid;
    if (tid < RELS) cnt[tid] = 0;
    __syncthreads();

    int t0 = -1;
    if (e < E) { t0 = et[e]; atomicAdd(&cnt[t0], 1); }
    __syncthreads();

    if (tid < RELS) {
        int v = cnt[tid];
        base[tid] = v ? atomicAdd(&g_cnt[tid], v) : 0;
        cnt[tid] = 0;
    }
    __syncthreads();

    if (t0 >= 0) {
        int p = base[t0] + atomicAdd(&cnt[t0], 1);
        g_edges[t0 * CAP + p] =
            (unsigned long long)(unsigned)src[e] |
            ((unsigned long long)(unsigned)dst[e] << 32);
    }
}

__global__ __launch_bounds__(128, 5)
void k_main(const float4* __restrict__ feat4, const float* __restrict__ W,
            float* __restrict__ out) {
    int r = blockIdx.x >> 5;            // MAXK = 32
    int kk = blockIdx.x & (MAXK - 1);
    int cnt = g_cnt[r];
    int segs = kk * EPB;
    int tid = threadIdx.x;

    if (segs < cnt) {                   // block-uniform
        int nwork = min(cnt - segs, EPB);
        const unsigned long long* eb = g_edges + (size_t)r * CAP;

        // Per-warp 5120B: A_hi[32 x 80B] + A_lo; reused as f32 stage later.
        __shared__ float4 warpbuf[4][320];
        // B tiles: Bhi [n=32][k=32] bf16 (80B rows) + Blo.
        __shared__ float4 Bsm[320];
        __shared__ unsigned long long pkst[EPB];

        int w = tid >> 5, l = tid & 31;

        // ---- B conversion: Bsm[n][k] = split-bf16 of W[r][k][n] ----
        {
            char* Bhi = (char*)Bsm;
            char* Blo = Bhi + 2560;
            int n = tid & 31;
            int ks8 = (tid >> 5) * 8;
            const float* Wr = W + r * 1024;
            #pragma unroll
            for (int j = 0; j < 4; j++) {
                int k = ks8 + 2 * j;
                float w0 = Wr[k * 32 + n];
                float w1 = Wr[(k + 1) * 32 + n];
                uint32_t hi2 = pack_bf16x2(w0, w1);
                float h0 = __uint_as_float(hi2 << 16);
                float h1 = __uint_as_float(hi2 & 0xFFFF0000u);
                uint32_t lo2 = pack_bf16x2(w0 - h0, w1 - h1);
                *(uint32_t*)(Bhi + n * 80 + k * 2) = hi2;
                *(uint32_t*)(Blo + n * 80 + k * 2) = lo2;
            }
        }
        // pkst preload (coalesced, clamped)
        for (int i = tid; i < EPB; i += 128)
            pkst[i] = eb[segs + min(i, nwork - 1)];
        __syncthreads();

        int eh4 = l >> 3, c = l & 7;                // gather/scatter lanes
        int rowl = (l & 7) + ((l >> 3) & 1) * 8;    // ldmatrix A row
        int kcl = l >> 4;                           // ldmatrix A k-chunk
        int g4 = l >> 2, tig = l & 3;               // mma fragment coords

        // ---- prefetch tile 0 feats ----
        float4 F[8];
        {
            int tbase = w * 64;
            #pragma unroll
            for (int g = 0; g < 8; g++) {
                int idx = min(tbase + g * 4 + eh4, nwork - 1);
                int s = (int)(unsigned)pkst[idx];
                F[g] = feat4[s * 8 + c];
            }
        }

        uint32_t Bbase = smem_u32(Bsm);
        int mi = l >> 3;
        int nr = ((mi >> 1) << 3) + (l & 7);
        int kc = mi & 1;

        uint32_t Abase = smem_u32(&warpbuf[w][0]);
        char* Ahi = (char*)&warpbuf[w][0];
        char* Alo = Ahi + 2560;
        float* stg = (float*)&warpbuf[w][0];

        #pragma unroll 1
        for (int t = 0; t < 2; t++) {
            int tbase = w * 64 + t * 32;
            if (tbase >= nwork) break;              // warp-uniform

            // ---- convert prefetched feats -> split-bf16 A tiles ----
            #pragma unroll
            for (int g = 0; g < 8; g++) {
                int row = g * 4 + eh4;
                float4 f = F[g];
                uint32_t hxy = pack_bf16x2(f.x, f.y);
                uint32_t hzw = pack_bf16x2(f.z, f.w);
                float hx = __uint_as_float(hxy << 16);
                float hy = __uint_as_float(hxy & 0xFFFF0000u);
                float hz = __uint_as_float(hzw << 16);
                float hw = __uint_as_float(hzw & 0xFFFF0000u);
                uint32_t lxy = pack_bf16x2(f.x - hx, f.y - hy);
                uint32_t lzw = pack_bf16x2(f.z - hz, f.w - hw);
                *(uint2*)(Ahi + row * 80 + c * 8) = make_uint2(hxy, hzw);
                *(uint2*)(Alo + row * 80 + c * 8) = make_uint2(lxy, lzw);
            }

            // ---- issue next tile's gather (hides behind MMA) ----
            if (t == 0 && tbase + 32 < nwork) {
                #pragma unroll
                for (int g = 0; g < 8; g++) {
                    int idx = min(tbase + 32 + g * 4 + eh4, nwork - 1);
                    int s = (int)(unsigned)pkst[idx];
                    F[g] = feat4[s * 8 + c];
                }
            }
            __syncwarp();

            // ---- B fragments for this tile (transient) ----
            uint32_t Bhf[2][4][2], Blf[2][4][2];
            #pragma unroll
            for (int ks = 0; ks < 2; ks++)
                #pragma unroll
                for (int j2 = 0; j2 < 2; j2++) {
                    uint32_t ad = Bbase + (uint32_t)((nr + j2 * 16) * 80 +
                                                     (2 * ks + kc) * 16);
                    uint32_t f[4];
                    ldsm4(ad, f);
                    Bhf[ks][2 * j2][0] = f[0]; Bhf[ks][2 * j2][1] = f[1];
                    Bhf[ks][2 * j2 + 1][0] = f[2]; Bhf[ks][2 * j2 + 1][1] = f[3];
                    ldsm4(ad + 2560u, f);
                    Blf[ks][2 * j2][0] = f[0]; Blf[ks][2 * j2][1] = f[1];
                    Blf[ks][2 * j2 + 1][0] = f[2]; Blf[ks][2 * j2 + 1][1] = f[3];
                }

            // ---- MMA: D = Ahi*Bhi + Ahi*Blo + Alo*Bhi ----
            float D[2][4][4];
            #pragma unroll
            for (int mb = 0; mb < 2; mb++)
                #pragma unroll
                for (int nb = 0; nb < 4; nb++)
                    #pragma unroll
                    for (int q = 0; q < 4; q++) D[mb][nb][q] = 0.f;

            uint32_t Af[2][2][4];                    // [mb][ks][4]
            #pragma unroll
            for (int mb = 0; mb < 2; mb++)
                #pragma unroll
                for (int ks = 0; ks < 2; ks++)
                    ldsm4(Abase + (uint32_t)((mb * 16 + rowl) * 80 +
                                             (ks * 2 + kcl) * 16), Af[mb][ks]);
            #pragma unroll
            for (int mb = 0; mb < 2; mb++)
                #pragma unroll
                for (int nb = 0; nb < 4; nb++)
                    #pragma unroll
                    for (int ks = 0; ks < 2; ks++) {
                        mma16816(D[mb][nb], Af[mb][ks], Bhf[ks][nb]);
                        mma16816(D[mb][nb], Af[mb][ks], Blf[ks][nb]);
                    }
            #pragma unroll
            for (int mb = 0; mb < 2; mb++)
                #pragma unroll
                for (int ks = 0; ks < 2; ks++)
                    ldsm4(Abase + 2560u + (uint32_t)((mb * 16 + rowl) * 80 +
                                                     (ks * 2 + kcl) * 16),
                          Af[mb][ks]);
            #pragma unroll
            for (int mb = 0; mb < 2; mb++)
                #pragma unroll
                for (int nb = 0; nb < 4; nb++)
                    #pragma unroll
                    for (int ks = 0; ks < 2; ks++)
                        mma16816(D[mb][nb], Af[mb][ks], Bhf[ks][nb]);
            __syncwarp();   // A tiles consumed; region becomes the f32 stage

            // ---- epilogue: fragment -> stage (stride 36 f32) ----
            #pragma unroll
            for (int mb = 0; mb < 2; mb++)
                #pragma unroll
                for (int nb = 0; nb < 4; nb++) {
                    *(float2*)(stg + (mb * 16 + g4) * 36 + nb * 8 + tig * 2) =
                        make_float2(D[mb][nb][0], D[mb][nb][1]);
                    *(float2*)(stg + (mb * 16 + g4 + 8) * 36 + nb * 8 + tig * 2) =
                        make_float2(D[mb][nb][2], D[mb][nb][3]);
                }
            __syncwarp();

            // ---- cooperative scatter: 4 dst rows per red.v4 ----
            #pragma unroll
            for (int g = 0; g < 8; g++) {
                int row = g * 4 + eh4;
                int idx = tbase + row;
                if (idx < nwork) {
                    int d = (int)(pkst[idx] >> 32);
                    float4 a = *(float4*)(stg + row * 36 + c * 4);
                    float* pp = out + (size_t)d * 32 + c * 4;
                    asm volatile("red.global.add.v4.f32 [%0], {%1,%2,%3,%4};"
                                 :: "l"(pp), "f"(a.x), "f"(a.y), "f"(a.z),
                                    "f"(a.w) : "memory");
                }
            }
            __syncwarp();   // stage freed before next tile's A-tile stores
        }
    }

    // ---- completion counter: last block restores g_cnt/g_done to zero ----
    __syncthreads();
    if (tid == 0) {
        __threadfence();
        int old = atomicAdd(&g_done, 1);
        if (old == NBLK - 1) {
            #pragma unroll
            for (int i = 0; i < RELS; i++) g_cnt[i] = 0;
            g_done = 0;
            __threadfence();
        }
    }
}

extern "C" void kernel_launch(void* const* d_in, const int* in_sizes, int n_in,
                              void* d_out, int out_size) {
    const float* feat = (const float*)d_in[0];
    const float* W    = (const float*)d_in[1];
    const int*   src  = (const int*)d_in[2];
    const int*   dst  = (const int*)d_in[3];
    const int*   et   = (const int*)d_in[4];
    int E = in_sizes[2];

    k_scatter<<<(E + SCHUNK - 1) / SCHUNK, 256>>>(src, dst, et, E,
                                                  (float4*)d_out, out_size / 4);
    k_main<<<NBLK, 128>>>((const float4*)feat, W, (float*)d_out);
}

// round 17
// speedup vs baseline: 1.1130x; 1.1130x over previous
#include <cuda_runtime.h>
#include <cstdint>

// RGCNHighMem: out[dst] += feat[src] @ W[etype]
// v17: v14 (best: split-bf16 mma.sync, EPB 256, rolling prefetch, occ 4,
// persistent Bhi fragments) + W split-conversion hoisted into k_scatter:
// first 64 scatter blocks write bf16 hi/lo B tiles to g_B; k_main just
// flat-copies 5KB (L2-hot) into smem instead of converting per block.

#define RELS   64
#define EPB    256
#define SCHUNK 256
#define CAP    8192
#define MAXK   (CAP / EPB)  // 32

__device__ int g_cnt[RELS];
__device__ unsigned long long g_edges[RELS * CAP];  // packed (src | dst<<32)
__device__ uint4 g_B[RELS * 320];   // per rel: Bhi[32][80B] + Blo[32][80B]

__device__ __forceinline__ uint32_t smem_u32(const void* p) {
    uint32_t a;
    asm("{ .reg .u64 t; cvta.to.shared.u64 t, %1; cvt.u32.u64 %0, t; }"
        : "=r"(a) : "l"(p));
    return a;
}
__device__ __forceinline__ uint32_t pack_bf16x2(float lo, float hi) {
    uint32_t r;
    asm("cvt.rn.bf16x2.f32 %0, %1, %2;" : "=r"(r) : "f"(hi), "f"(lo));
    return r;
}
__device__ __forceinline__ void ldsm4(uint32_t a, uint32_t* f) {
    asm volatile("ldmatrix.sync.aligned.m8n8.x4.shared.b16 {%0,%1,%2,%3}, [%4];"
                 : "=r"(f[0]), "=r"(f[1]), "=r"(f[2]), "=r"(f[3]) : "r"(a));
}
__device__ __forceinline__ void mma16816(float* d, const uint32_t* a,
                                         const uint32_t* b) {
    asm volatile(
        "mma.sync.aligned.m16n8k16.row.col.f32.bf16.bf16.f32 "
        "{%0,%1,%2,%3}, {%4,%5,%6,%7}, {%8,%9}, {%0,%1,%2,%3};"
        : "+f"(d[0]), "+f"(d[1]), "+f"(d[2]), "+f"(d[3])
        : "r"(a[0]), "r"(a[1]), "r"(a[2]), "r"(a[3]), "r"(b[0]), "r"(b[1]));
}

// Single-pass scatter + d_out zeroing + (first 64 blocks) W split-conversion.
__global__ __launch_bounds__(256)
void k_scatter(const int* __restrict__ src, const int* __restrict__ dst,
               const int* __restrict__ et, int E, const float* __restrict__ W,
               float4* __restrict__ out4, int nout4) {
    __shared__ int cnt[RELS], base[RELS];
    int tid = threadIdx.x;

    for (int i = blockIdx.x * 256 + tid; i < nout4; i += gridDim.x * 256)
        out4[i] = make_float4(0.f, 0.f, 0.f, 0.f);

    // W split-conversion: block rr (< 64) converts relation rr.
    if (blockIdx.x < RELS) {
        int rr = blockIdx.x;
        char* Bhi = (char*)(g_B + rr * 320);
        char* Blo = Bhi + 2560;
        int n = tid & 31;
        int k0 = (tid >> 5) * 4;             // 8 groups x 4 k-values
        const float* Wr = W + rr * 1024;
        #pragma unroll
        for (int j = 0; j < 2; j++) {
            int k = k0 + 2 * j;
            float w0 = Wr[k * 32 + n];
            float w1 = Wr[(k + 1) * 32 + n];
            uint32_t hi2 = pack_bf16x2(w0, w1);
            float h0 = __uint_as_float(hi2 << 16);
            float h1 = __uint_as_float(hi2 & 0xFFFF0000u);
            uint32_t lo2 = pack_bf16x2(w0 - h0, w1 - h1);
            *(uint32_t*)(Bhi + n * 80 + k * 2) = hi2;
            *(uint32_t*)(Blo + n * 80 + k * 2) = lo2;
        }
    }

    int e = blockIdx.x * SCHUNK + tid;
    if (tid < RELS) cnt[tid] = 0;
    __syncthreads();

    int t0 = -1;
    if (e < E) { t0 = et[e]; atomicAdd(&cnt[t0], 1); }
    __syncthreads();

    if (tid < RELS) {
        int v = cnt[tid];
        base[tid] = v ? atomicAdd(&g_cnt[tid], v) : 0;
        cnt[tid] = 0;
    }
    __syncthreads();

    if (t0 >= 0) {
        int p = base[t0] + atomicAdd(&cnt[t0], 1);
        g_edges[t0 * CAP + p] =
            (unsigned long long)(unsigned)src[e] |
            ((unsigned long long)(unsigned)dst[e] << 32);
    }
}

__global__ __launch_bounds__(128, 4)
void k_main(const float4* __restrict__ feat4, float* __restrict__ out) {
    int r = blockIdx.x >> 5;            // MAXK = 32
    int kk = blockIdx.x & (MAXK - 1);
    int cnt = g_cnt[r];
    int segs = kk * EPB;
    if (segs >= cnt) return;            // block-uniform, before syncthreads
    int nwork = min(cnt - segs, EPB);
    const unsigned long long* eb = g_edges + (size_t)r * CAP;

    // Per-warp 5120B: A_hi[32 rows x 80B] + A_lo; reused as f32 stage later.
    __shared__ float4 warpbuf[4][320];
    // B tiles: Bhi [n=32][k=32] bf16 (80B rows) + Blo (pre-converted).
    __shared__ float4 Bsm[320];
    __shared__ unsigned long long pkst[EPB];

    int tid = threadIdx.x;
    int w = tid >> 5, l = tid & 31;

    // ---- B tiles: flat copy from pre-converted g_B (L2-hot) ----
    {
        const uint4* Bg = g_B + r * 320;
        uint4* Bs = (uint4*)Bsm;
        #pragma unroll
        for (int i = 0; i < 2; i++) Bs[tid + i * 128] = Bg[tid + i * 128];
        if (tid < 64) Bs[tid + 256] = Bg[tid + 256];
    }
    // pkst preload (coalesced, clamped)
    for (int i = tid; i < EPB; i += 128)
        pkst[i] = eb[segs + min(i, nwork - 1)];
    __syncthreads();

    int eh4 = l >> 3, c = l & 7;                    // gather/scatter lanes
    int rowl = (l & 7) + ((l >> 3) & 1) * 8;        // ldmatrix A row
    int kcl = l >> 4;                               // ldmatrix A k-chunk
    int g4 = l >> 2, tig = l & 3;                   // mma fragment coords

    // ---- prefetch tile 0 feats (hides behind B-fragment setup) ----
    float4 F[8];
    {
        int tbase = w * 64;
        #pragma unroll
        for (int g = 0; g < 8; g++) {
            int idx = min(tbase + g * 4 + eh4, nwork - 1);
            int s = (int)(unsigned)pkst[idx];
            F[g] = feat4[s * 8 + c];
        }
    }

    // ---- Bhi fragments -> registers (persist); Blo re-ldsm'd per tile ----
    uint32_t Bbase = smem_u32(Bsm);
    int mi = l >> 3;
    int nr = ((mi >> 1) << 3) + (l & 7);
    int kc = mi & 1;
    uint32_t Bh[2][4][2];
    #pragma unroll
    for (int ks = 0; ks < 2; ks++)
        #pragma unroll
        for (int j2 = 0; j2 < 2; j2++) {
            uint32_t ad = Bbase + (uint32_t)((nr + j2 * 16) * 80 +
                                             (2 * ks + kc) * 16);
            uint32_t f[4];
            ldsm4(ad, f);
            Bh[ks][2 * j2][0] = f[0]; Bh[ks][2 * j2][1] = f[1];
            Bh[ks][2 * j2 + 1][0] = f[2]; Bh[ks][2 * j2 + 1][1] = f[3];
        }

    uint32_t Abase = smem_u32(&warpbuf[w][0]);
    char* Ahi = (char*)&warpbuf[w][0];
    char* Alo = Ahi + 2560;
    float* stg = (float*)&warpbuf[w][0];

    #pragma unroll 1
    for (int t = 0; t < 2; t++) {
        int tbase = w * 64 + t * 32;
        if (tbase >= nwork) break;                  // warp-uniform

        // ---- convert prefetched feats -> split-bf16 A tiles ----
        #pragma unroll
        for (int g = 0; g < 8; g++) {
            int row = g * 4 + eh4;
            float4 f = F[g];
            uint32_t hxy = pack_bf16x2(f.x, f.y);
            uint32_t hzw = pack_bf16x2(f.z, f.w);
            float hx = __uint_as_float(hxy << 16);
            float hy = __uint_as_float(hxy & 0xFFFF0000u);
            float hz = __uint_as_float(hzw << 16);
            float hw = __uint_as_float(hzw & 0xFFFF0000u);
            uint32_t lxy = pack_bf16x2(f.x - hx, f.y - hy);
            uint32_t lzw = pack_bf16x2(f.z - hz, f.w - hw);
            *(uint2*)(Ahi + row * 80 + c * 8) = make_uint2(hxy, hzw);
            *(uint2*)(Alo + row * 80 + c * 8) = make_uint2(lxy, lzw);
        }

        // ---- issue next tile's gather (latency hides behind MMA) ----
        if (t == 0 && tbase + 32 < nwork) {
            #pragma unroll
            for (int g = 0; g < 8; g++) {
                int idx = min(tbase + 32 + g * 4 + eh4, nwork - 1);
                int s = (int)(unsigned)pkst[idx];
                F[g] = feat4[s * 8 + c];
            }
        }
        __syncwarp();

        // ---- Blo fragments for this tile (transient) ----
        uint32_t Blf[2][4][2];
        #pragma unroll
        for (int ks = 0; ks < 2; ks++)
            #pragma unroll
            for (int j2 = 0; j2 < 2; j2++) {
                uint32_t ad = Bbase + 2560u +
                    (uint32_t)((nr + j2 * 16) * 80 + (2 * ks + kc) * 16);
                uint32_t f[4];
                ldsm4(ad, f);
                Blf[ks][2 * j2][0] = f[0]; Blf[ks][2 * j2][1] = f[1];
                Blf[ks][2 * j2 + 1][0] = f[2]; Blf[ks][2 * j2 + 1][1] = f[3];
            }

        // ---- MMA: D = Ahi*Bhi + Ahi*Blo + Alo*Bhi ----
        float D[2][4][4];
        #pragma unroll
        for (int mb = 0; mb < 2; mb++)
            #pragma unroll
            for (int nb = 0; nb < 4; nb++)
                #pragma unroll
                for (int q = 0; q < 4; q++) D[mb][nb][q] = 0.f;

        uint32_t Af[2][2][4];                        // [mb][ks][4]
        #pragma unroll
        for (int mb = 0; mb < 2; mb++)
            #pragma unroll
            for (int ks = 0; ks < 2; ks++)
                ldsm4(Abase + (uint32_t)((mb * 16 + rowl) * 80 +
                                         (ks * 2 + kcl) * 16), Af[mb][ks]);
        #pragma unroll
        for (int mb = 0; mb < 2; mb++)
            #pragma unroll
            for (int nb = 0; nb < 4; nb++)
                #pragma unroll
                for (int ks = 0; ks < 2; ks++) {
                    mma16816(D[mb][nb], Af[mb][ks], Bh[ks][nb]);
                    mma16816(D[mb][nb], Af[mb][ks], Blf[ks][nb]);
                }
        #pragma unroll
        for (int mb = 0; mb < 2; mb++)
            #pragma unroll
            for (int ks = 0; ks < 2; ks++)
                ldsm4(Abase + 2560u + (uint32_t)((mb * 16 + rowl) * 80 +
                                                 (ks * 2 + kcl) * 16),
                      Af[mb][ks]);
        #pragma unroll
        for (int mb = 0; mb < 2; mb++)
            #pragma unroll
            for (int nb = 0; nb < 4; nb++)
                #pragma unroll
                for (int ks = 0; ks < 2; ks++)
                    mma16816(D[mb][nb], Af[mb][ks], Bh[ks][nb]);
        __syncwarp();   // A tiles consumed; region becomes the f32 stage

        // ---- epilogue: fragment -> stage (stride 36 f32 = 144B) ----
        #pragma unroll
        for (int mb = 0; mb < 2; mb++)
            #pragma unroll
            for (int nb = 0; nb < 4; nb++) {
                *(float2*)(stg + (mb * 16 + g4) * 36 + nb * 8 + tig * 2) =
                    make_float2(D[mb][nb][0], D[mb][nb][1]);
                *(float2*)(stg + (mb * 16 + g4 + 8) * 36 + nb * 8 + tig * 2) =
                    make_float2(D[mb][nb][2], D[mb][nb][3]);
            }
        __syncwarp();

        // ---- cooperative scatter: 4 dst rows per red.v4 ----
        #pragma unroll
        for (int g = 0; g < 8; g++) {
            int row = g * 4 + eh4;
            int idx = tbase + row;
            if (idx < nwork) {
                int d = (int)(pkst[idx] >> 32);
                float4 a = *(float4*)(stg + row * 36 + c * 4);
                float* pp = out + (size_t)d * 32 + c * 4;
                asm volatile("red.global.add.v4.f32 [%0], {%1,%2,%3,%4};"
                             :: "l"(pp), "f"(a.x), "f"(a.y), "f"(a.z), "f"(a.w)
                             : "memory");
            }
        }
        __syncwarp();   // stage freed before next tile's A-tile stores
    }
}

extern "C" void kernel_launch(void* const* d_in, const int* in_sizes, int n_in,
                              void* d_out, int out_size) {
    const float* feat = (const float*)d_in[0];
    const float* W    = (const float*)d_in[1];
    const int*   src  = (const int*)d_in[2];
    const int*   dst  = (const int*)d_in[3];
    const int*   et   = (const int*)d_in[4];
    int E = in_sizes[2];

    void* cnt_addr = nullptr;
    cudaGetSymbolAddress(&cnt_addr, g_cnt);

    cudaMemsetAsync(cnt_addr, 0, RELS * sizeof(int), 0);
    k_scatter<<<(E + SCHUNK - 1) / SCHUNK, 256>>>(src, dst, et, E, W,
                                                  (float4*)d_out, out_size / 4);
    k_main<<<RELS * MAXK, 128>>>((const float4*)feat, (float*)d_out);
}